// round 5
// baseline (speedup 1.0000x reference)
#include <cuda_runtime.h>
#include <math.h>
#include <float.h>
#include <stdint.h>

#define VOCAB  32000
#define HID    1024
#define BEAM   16
#define TSTEPS 16
#define NB     148      // persistent blocks (1 per SM, co-resident)
#define NCHUNK 8
#define CHSZ   4000
#define G2_TILES 250
#define G2_COLS  128
#define DSMEM  65536

// ---------------- scratch (device globals; no allocation) ----------------
__device__ float g_logits[BEAM][VOCAB];          // final logits (2 MB)
__device__ float g_h[BEAM][HID];                 // hidden state (single buffer)
__device__ float g_part1[64][BEAM][HID];         // gemm1 partials (4 MB)
__device__ float g_cv[BEAM][NCHUNK][16];
__device__ int   g_ci[BEAM][NCHUNK][16];
__device__ float g_cm[BEAM][NCHUNK];
__device__ float g_cs[BEAM][NCHUNK];
__device__ float g_beam_lps[BEAM];
__device__ int   g_beam_seq[TSTEPS][BEAM];
__device__ float g_beam_seq_lp[TSTEPS][BEAM];
__device__ int   g_sel_c[BEAM];
__device__ int   g_sel_q[BEAM];
__device__ unsigned g_bar[96];                   // grid-barrier slots (zeroed per launch)
__device__ unsigned g_tick[TSTEPS];              // gemm2 work tickets (zeroed per launch)

// ---------------- helpers ----------------
__device__ __forceinline__ bool better(float va, int ia, float vb, int ib) {
    return (va > vb) || (va == vb && ia < ib);
}
__device__ __forceinline__ unsigned long long pack2(float x, float y) {
    unsigned long long r;
    asm("mov.b64 %0, {%1, %2};" : "=l"(r)
        : "r"(__float_as_uint(x)), "r"(__float_as_uint(y)));
    return r;
}
__device__ __forceinline__ void unpack2(unsigned long long v, float &x, float &y) {
    unsigned int a, b;
    asm("mov.b64 {%0, %1}, %2;" : "=r"(a), "=r"(b) : "l"(v));
    x = __uint_as_float(a); y = __uint_as_float(b);
}
__device__ __forceinline__ void fma2(unsigned long long &d, unsigned long long a,
                                     unsigned long long b) {
    asm("fma.rn.f32x2 %0, %1, %2, %3;" : "=l"(d) : "l"(a), "l"(b), "l"(d));
}
__device__ __forceinline__ float tanh_acc(float x) {
    float ax = fabsf(x);
    float e  = __expf(2.0f * ax);
    float r  = 1.0f - 2.0f / (e + 1.0f);
    return copysignf(r, x);
}
__device__ __forceinline__ void merge16(const float* av, const int* ai,
                                        const float* bv, const int* bi,
                                        float* ov, int* oi) {
    int pa = 0, pb = 0;
#pragma unroll
    for (int k = 0; k < 16; k++) {
        float x1 = av[pa]; int i1 = ai[pa];
        float x2 = bv[pb]; int i2 = bi[pb];
        bool ta = better(x1, i1, x2, i2);
        ov[k] = ta ? x1 : x2; oi[k] = ta ? i1 : i2;
        pa += ta; pb += !ta;
    }
}

// device-wide barrier: all NB co-resident blocks arrive; fresh slot per use
__device__ __forceinline__ void gbar(int id) {
    __syncthreads();
    if (threadIdx.x == 0) {
        __threadfence();                       // release all prior writes
        atomicAdd(&g_bar[id], 1u);
        while (((volatile unsigned*)g_bar)[id] < NB) __nanosleep(128);
        __threadfence();                       // acquire before dependent reads
    }
    __syncthreads();
}

// ---------------- init (separate node: zero counters, seed state) ----------------
__global__ void init_kernel(const float* __restrict__ state) {
    int i = blockIdx.x * 256 + threadIdx.x;
    if (i < BEAM * HID) ((float*)g_h)[i] = state[i];
    if (i < BEAM) g_beam_lps[i] = 0.f;
    if (i < 96) g_bar[i] = 0u;
    if (i < TSTEPS) g_tick[i] = 0u;
}

// ---------------- the persistent kernel ----------------
extern __shared__ char dynsm[];

struct SelSm {
    float Av[BEAM][NCHUNK][16]; int Ai[BEAM][NCHUNK][16];
    float Bv[BEAM][NCHUNK/2][16]; int Bi[BEAM][NCHUNK/2][16];
    float tv[BEAM][16]; int ti[BEAM][16];
    float lzM[BEAM], lzL[BEAM];
    float cand[256];
    float selv[16]; int seli[16];
    int q_s[16], c_s[16]; float r_s[16], p_s[16];
    int oldseq[TSTEPS*BEAM]; float oldlp[TSTEPS*BEAM];
};

__global__ void __launch_bounds__(256, 1) beam_persistent(
    const float* __restrict__ logprobs0,
    const float* __restrict__ embed,
    const float* __restrict__ Wih,
    const float* __restrict__ Whh,
    const float* __restrict__ bias,
    const float* __restrict__ Wout,
    float* __restrict__ out, int out_size)
{
    const int bx = blockIdx.x, tid = threadIdx.x;
    int bar = 0;
    __shared__ int s_tile;
    __shared__ int s_selc[16], s_selq[16];

    for (int t = 0; t < TSTEPS; t++) {
        // ======== P1: per-(chunk,beam) scan: lse + top16 (blocks 0..127) ========
        if (bx < NCHUNK * BEAM) {
            float (*sv)[16] = (float (*)[16])(dynsm);
            int   (*si)[16] = (int (*)[16])(dynsm + 16384);
            float *rm = (float*)(dynsm + 32768);
            float *rs = (float*)(dynsm + 32768 + 1024);
            int chunk = bx & (NCHUNK - 1), b = bx >> 3;
            int base = chunk * CHSZ, end = base + CHSZ;

            float lv[16]; int li[16];
#pragma unroll
            for (int j = 0; j < 16; j++) { lv[j] = -INFINITY; li[j] = 0x7fffffff; }
            float m = -INFINITY, s = 0.f;

            for (int i = base + tid; i < end; i += 256) {
                float x = (t == 0) ? logprobs0[(size_t)b * VOCAB + i]
                                   : __ldcg(&g_logits[b][i]);
                if (x > m) { s = s * __expf(m - x) + 1.f; m = x; }
                else       { s += __expf(x - m); }
                float v = (i == VOCAB - 1) ? x - 1000.f : x;
                if (better(v, i, lv[15], li[15])) {
#pragma unroll
                    for (int j = 15; j >= 1; j--) {
                        bool cj  = better(v, i, lv[j],     li[j]);
                        bool cjm = better(v, i, lv[j - 1], li[j - 1]);
                        float nv = cjm ? lv[j - 1] : v;
                        int   ni = cjm ? li[j - 1] : i;
                        lv[j] = cj ? nv : lv[j];
                        li[j] = cj ? ni : li[j];
                    }
                    bool c0 = better(v, i, lv[0], li[0]);
                    if (c0) { lv[0] = v; li[0] = i; }
                }
            }
#pragma unroll
            for (int j = 0; j < 16; j++) { sv[tid][j] = lv[j]; si[tid][j] = li[j]; }
            rm[tid] = m; rs[tid] = s;
            __syncthreads();
            for (int stride = 128; stride >= 1; stride >>= 1) {
                if (tid < stride) {
                    float ov[16]; int oi[16];
                    merge16(sv[tid], si[tid], sv[tid + stride], si[tid + stride], ov, oi);
#pragma unroll
                    for (int j = 0; j < 16; j++) { sv[tid][j] = ov[j]; si[tid][j] = oi[j]; }
                    float m2 = rm[tid + stride], s2 = rs[tid + stride];
                    float m1 = rm[tid], s1 = rs[tid];
                    float M = fmaxf(m1, m2);
                    rs[tid] = s1 * __expf(m1 - M) + s2 * __expf(m2 - M);
                    rm[tid] = M;
                }
                __syncthreads();
            }
            if (tid < 16) {
                g_cv[b][chunk][tid] = sv[0][tid];
                g_ci[b][chunk][tid] = si[0][tid];
            }
            if (tid == 0) { g_cm[b][chunk] = rm[0]; g_cs[b][chunk] = rs[0]; }
        }
        gbar(bar++);

        // ======== P2: merge + normalize + global select (block 0) ========
        if (bx == 0) {
            SelSm* S = (SelSm*)dynsm;
            for (int idx = tid; idx < BEAM * NCHUNK * 16; idx += 256) {
                ((float*)S->Av)[idx] = __ldcg(&((const float*)g_cv)[idx]);
                ((int*)S->Ai)[idx]   = __ldcg(&((const int*)g_ci)[idx]);
            }
            for (int idx = tid; idx < t * BEAM; idx += 256) {
                S->oldseq[idx] = ((const int*)g_beam_seq)[idx];
                S->oldlp[idx]  = ((const float*)g_beam_seq_lp)[idx];
            }
            __syncthreads();

            if (tid < BEAM * 4) {
                int b = tid >> 2, j = tid & 3;
                merge16(S->Av[b][2*j], S->Ai[b][2*j], S->Av[b][2*j+1], S->Ai[b][2*j+1],
                        S->Bv[b][j], S->Bi[b][j]);
            }
            if (tid >= 128 && tid < 128 + BEAM) {
                int b = tid - 128;
                float M = __ldcg(&g_cm[b][0]);
#pragma unroll
                for (int c = 1; c < NCHUNK; c++) M = fmaxf(M, __ldcg(&g_cm[b][c]));
                float Ssum = 0.f;
#pragma unroll
                for (int c = 0; c < NCHUNK; c++)
                    Ssum += __ldcg(&g_cs[b][c]) * __expf(__ldcg(&g_cm[b][c]) - M);
                S->lzM[b] = M; S->lzL[b] = logf(Ssum);
            }
            __syncthreads();
            if (tid < BEAM * 2) {
                int b = tid >> 1, j = tid & 1;
                merge16(S->Bv[b][2*j], S->Bi[b][2*j], S->Bv[b][2*j+1], S->Bi[b][2*j+1],
                        S->Av[b][j], S->Ai[b][j]);
            }
            __syncthreads();
            if (tid < BEAM) {
                merge16(S->Av[tid][0], S->Ai[tid][0], S->Av[tid][1], S->Ai[tid][1],
                        S->Bv[tid][0], S->Bi[tid][0]);
            }
            __syncthreads();

            {
                int b = tid >> 4, j = tid & 15;
                float v = S->Bv[b][0][j];
                int   i = S->Bi[b][0][j];
                float outv;
                if (t == 0) {
                    outv = v;
                } else {
                    float mm = S->lzM[b], lse = S->lzL[b];
                    if (i == VOCAB - 1)
                        outv = ((__ldcg(&g_logits[b][VOCAB - 1]) - mm) - lse) - 1000.f;
                    else
                        outv = (v - mm) - lse;
                }
                S->tv[b][j] = outv; S->ti[b][j] = i;
            }
            __syncthreads();

            {
                int qi = tid >> 4, j = tid & 15;
                float cp = g_beam_lps[qi] + S->tv[qi][j];
                if (t == 0 && qi != 0) cp = -INFINITY;
                S->cand[tid] = cp;
            }
            __syncthreads();

            if (tid < 32) {
                for (int r = 0; r < 16; r++) {
                    float bv = -INFINITY; int bi = 0x7fffffff;
#pragma unroll
                    for (int k2 = 0; k2 < 8; k2++) {
                        int idx = tid * 8 + k2;
                        float v = S->cand[idx];
                        if (better(v, idx, bv, bi)) { bv = v; bi = idx; }
                    }
#pragma unroll
                    for (int off = 16; off >= 1; off >>= 1) {
                        float ov = __shfl_down_sync(0xffffffffu, bv, off);
                        int   oi = __shfl_down_sync(0xffffffffu, bi, off);
                        if (better(ov, oi, bv, bi)) { bv = ov; bi = oi; }
                    }
                    bv = __shfl_sync(0xffffffffu, bv, 0);
                    bi = __shfl_sync(0xffffffffu, bi, 0);
                    if (tid == 0) { S->selv[r] = bv; S->seli[r] = bi; S->cand[bi] = -INFINITY; }
                    __syncwarp();
                }
                if (tid < 16) {
                    int fi = S->seli[tid];
                    int q = fi >> 4, col = fi & 15;
                    int c = S->ti[q][col];
                    float rr = S->tv[q][col];
                    S->q_s[tid] = q; S->c_s[tid] = c; S->r_s[tid] = rr;
                    bool done = (c == 0) || (t == TSTEPS - 1);
                    S->p_s[tid] = done ? -1000.f : S->selv[tid];
                }
            }
            __syncthreads();

            for (int idx = tid; idx < t * BEAM; idx += 256) {
                int row = idx >> 4, col = idx & 15;
                ((int*)g_beam_seq)[idx]      = S->oldseq[row * 16 + S->q_s[col]];
                ((float*)g_beam_seq_lp)[idx] = S->oldlp[row * 16 + S->q_s[col]];
            }
            if (tid < 16) {
                g_beam_seq[t][tid]    = S->c_s[tid];
                g_beam_seq_lp[t][tid] = S->r_s[tid];
                g_beam_lps[tid]       = S->p_s[tid];
                g_sel_c[tid] = S->c_s[tid];
                g_sel_q[tid] = S->q_s[tid];
            }
        }
        gbar(bar++);

        if (t < TSTEPS - 1) {
            // ======== P3: gemm1 partials (256 tiles over all blocks) ========
            if (tid < 16) {
                s_selc[tid] = __ldcg(&g_sel_c[tid]);
                s_selq[tid] = __ldcg(&g_sel_q[tid]);
            }
            __syncthreads();
            {
                float (*xs1)[16] = (float (*)[16])dynsm;   // [64][16]
                for (int tile = bx; tile < 256; tile += NB) {
                    int cb = tile >> 5, kp = tile & 31;
                    bool isHH = kp >= 16;
                    const float* W = isHH ? Whh : Wih;
                    int k0 = ((2 * kp) & 31) * 32;
                    for (int idx = tid; idx < 16 * 64; idx += 256) {
                        int bb = idx >> 6, kk = idx & 63;
                        int k = k0 + kk;
                        float xv = isHH ? __ldcg(&g_h[s_selq[bb]][k])
                                        : embed[(size_t)s_selc[bb] * HID + k];
                        xs1[kk][bb] = xv;
                    }
                    __syncthreads();
                    int half = tid >> 7;
                    int o = cb * 128 + (tid & 127);
                    int ks = 2 * kp + half;
                    int kl0 = half * 32;
                    float w[32];
                    {
                        const float* wp = W + (size_t)(k0 + kl0) * HID + o;
#pragma unroll
                        for (int j = 0; j < 32; j++) w[j] = wp[(size_t)j * HID];
                    }
                    unsigned long long acc[8];
#pragma unroll
                    for (int p = 0; p < 8; p++) acc[p] = 0ull;
#pragma unroll
                    for (int kk = 0; kk < 32; kk++) {
                        unsigned long long w2 = pack2(w[kk], w[kk]);
                        const ulonglong2* xr = (const ulonglong2*)xs1[kl0 + kk];
                        ulonglong2 qa = xr[0], qb = xr[1], qc = xr[2], qd = xr[3];
                        fma2(acc[0], qa.x, w2); fma2(acc[1], qa.y, w2);
                        fma2(acc[2], qb.x, w2); fma2(acc[3], qb.y, w2);
                        fma2(acc[4], qc.x, w2); fma2(acc[5], qc.y, w2);
                        fma2(acc[6], qd.x, w2); fma2(acc[7], qd.y, w2);
                    }
#pragma unroll
                    for (int p = 0; p < 8; p++) {
                        float a, b2; unpack2(acc[p], a, b2);
                        g_part1[ks][2 * p][o]     = a;
                        g_part1[ks][2 * p + 1][o] = b2;
                    }
                    __syncthreads();
                }
            }
            gbar(bar++);

            // ======== P4: reduce + tanh (blocks 0..63) ========
            if (bx < 64) {
                int i = bx * 256 + tid, bb = i >> 10, o = i & 1023;
                float sih = 0.f, shh = 0.f;
#pragma unroll 8
                for (int ks = 0; ks < 32; ks++) sih += __ldcg(&g_part1[ks][bb][o]);
#pragma unroll 8
                for (int ks = 32; ks < 64; ks++) shh += __ldcg(&g_part1[ks][bb][o]);
                g_h[bb][o] = tanh_acc((sih + shh) + bias[o]);
            }
            gbar(bar++);

            // ======== P5: output projection (250 tiles, ticket-balanced) ========
            for (;;) {
                if (tid == 0) s_tile = (int)atomicAdd(&g_tick[t], 1u);
                __syncthreads();
                int tile = s_tile;
                __syncthreads();
                if (tile >= G2_TILES) break;

                float (*xs)[16] = (float (*)[16])dynsm;    // [1024][16]
                for (int idx = tid; idx < 4096; idx += 256) {
                    int b = idx & 15, k4 = idx >> 4;
                    float4 v = __ldcg((const float4*)&g_h[b][k4 * 4]);
                    xs[k4 * 4 + 0][b] = v.x; xs[k4 * 4 + 1][b] = v.y;
                    xs[k4 * 4 + 2][b] = v.z; xs[k4 * 4 + 3][b] = v.w;
                }
                __syncthreads();

                int ksp = tid >> 5, colg = tid & 31;
                int col = tile * G2_COLS + colg * 4;
                int k0  = ksp * 128;
                unsigned long long acc[4][8];
#pragma unroll
                for (int c = 0; c < 4; c++)
#pragma unroll
                    for (int p = 0; p < 8; p++) acc[c][p] = 0ull;

                const float* wp = Wout + (size_t)k0 * VOCAB + col;
#pragma unroll 4
                for (int kk = 0; kk < 128; kk++) {
                    float4 w = *(const float4*)wp; wp += VOCAB;
                    unsigned long long w0 = pack2(w.x, w.x), w1 = pack2(w.y, w.y);
                    unsigned long long w2 = pack2(w.z, w.z), w3 = pack2(w.w, w.w);
                    const ulonglong2* xr = (const ulonglong2*)xs[k0 + kk];
                    ulonglong2 qa = xr[0], qb = xr[1], qc = xr[2], qd = xr[3];
                    unsigned long long xv[8] = {qa.x, qa.y, qb.x, qb.y,
                                                qc.x, qc.y, qd.x, qd.y};
#pragma unroll
                    for (int p = 0; p < 8; p++) {
                        fma2(acc[0][p], xv[p], w0);
                        fma2(acc[1][p], xv[p], w1);
                        fma2(acc[2][p], xv[p], w2);
                        fma2(acc[3][p], xv[p], w3);
                    }
                }
                __syncthreads();   // xs done; reuse as reduce buffer

                float (*red)[BEAM][G2_COLS] = (float (*)[BEAM][G2_COLS])dynsm;
#pragma unroll
                for (int c = 0; c < 4; c++) {
#pragma unroll
                    for (int p = 0; p < 8; p++) {
                        float a, b2; unpack2(acc[c][p], a, b2);
                        red[ksp][2 * p][colg * 4 + c]     = a;
                        red[ksp][2 * p + 1][colg * 4 + c] = b2;
                    }
                }
                __syncthreads();
                for (int idx = tid; idx < G2_COLS * BEAM; idx += 256) {
                    int b = idx >> 7, c = idx & 127;
                    float s = 0.f;
#pragma unroll
                    for (int k = 0; k < 8; k++) s += red[k][b][c];
                    g_logits[b][tile * G2_COLS + c] = s;
                }
                __syncthreads();
            }
            gbar(bar++);
        }
    }

    // ======== output packing (block 0) ========
    if (bx == 0) {
        for (int i = tid; i < out_size; i += 256) {
            float v;
            if (i < TSTEPS * BEAM)            v = (float)((const int*)g_beam_seq)[i];
            else if (i < 2 * TSTEPS * BEAM)   v = ((const float*)g_beam_seq_lp)[i - TSTEPS * BEAM];
            else if (i < 2 * TSTEPS * BEAM + BEAM) v = g_beam_lps[i - 2 * TSTEPS * BEAM];
            else                              v = 0.f;
            out[i] = v;
        }
    }
}

extern "C" void kernel_launch(void* const* d_in, const int* in_sizes, int n_in,
                              void* d_out, int out_size) {
    const float* state    = (const float*)d_in[0];
    const float* logprobs = (const float*)d_in[1];
    const float* embed    = (const float*)d_in[2];
    const float* W_ih     = (const float*)d_in[3];
    const float* W_hh     = (const float*)d_in[4];
    const float* b        = (const float*)d_in[5];
    const float* W_out    = (const float*)d_in[6];

    cudaFuncSetAttribute(beam_persistent,
                         cudaFuncAttributeMaxDynamicSharedMemorySize, DSMEM);

    init_kernel<<<64, 256>>>(state);
    beam_persistent<<<NB, 256, DSMEM>>>(logprobs, embed, W_ih, W_hh, b, W_out,
                                        (float*)d_out, out_size);
}